// round 3
// baseline (speedup 1.0000x reference)
#include <cuda_runtime.h>
#include <math.h>

#define L_SEQ 4096
#define EDIM  512
#define HDIM  1024
#define G3    3072   // 3*HDIM
#define NCTA  128

// ---------------- scratch (static device globals; no allocation) -------------
__device__ float g_emb[(size_t)L_SEQ * EDIM];          // 8 MB
__device__ float g_gi [(size_t)L_SEQ * G3];            // 50 MB (reused per layer)
__device__ float g_ys [(size_t)L_SEQ * HDIM];          // 16 MB (layer-0 outputs)
__device__ float g_hv[2][HDIM];                        // double-buffered hidden state
__device__ unsigned g_done[2][NCTA];                   // per-CTA step tags

// ---------------- acquire/release helpers ------------------------------------
__device__ __forceinline__ unsigned ldacq_u32(const unsigned* p)
{
    unsigned v;
    asm volatile("ld.acquire.gpu.global.b32 %0, [%1];" : "=r"(v) : "l"(p) : "memory");
    return v;
}
__device__ __forceinline__ void strel_u32(unsigned* p, unsigned v)
{
    asm volatile("st.release.gpu.global.b32 [%0], %1;" :: "l"(p), "r"(v) : "memory");
}

__device__ __forceinline__ float fsig(float x)
{
    return 1.0f / (1.0f + __expf(-x));
}

// ---------------- embedding + max-norm --------------------------------------
__global__ void embed_kernel(const int* __restrict__ idx,
                             const float* __restrict__ E,
                             float* __restrict__ emb)
{
    int t = blockIdx.x;
    int id = idx[t];
    const float4* row = (const float4*)(E + (size_t)id * EDIM);
    float4 v = row[threadIdx.x];
    float ss = v.x*v.x + v.y*v.y + v.z*v.z + v.w*v.w;
    #pragma unroll
    for (int o = 16; o; o >>= 1) ss += __shfl_xor_sync(0xffffffffu, ss, o);
    __shared__ float red[4];
    int w = threadIdx.x >> 5;
    if ((threadIdx.x & 31) == 0) red[w] = ss;
    __syncthreads();
    float tot = red[0] + red[1] + red[2] + red[3];
    float scale = fminf(1.0f, 1.0f / fmaxf(sqrtf(tot), 1e-7f));
    v.x *= scale; v.y *= scale; v.z *= scale; v.w *= scale;
    ((float4*)(emb + (size_t)t * EDIM))[threadIdx.x] = v;
}

// ---------------- fp32 GEMM: C[M,N] = A[M,K] @ B[N,K]^T + bias[N] -----------
__global__ void __launch_bounds__(256) gemm_tn(const float* __restrict__ A,
                                               const float* __restrict__ B,
                                               const float* __restrict__ bias,
                                               float* __restrict__ C,
                                               int M, int N, int K)
{
    __shared__ float As[16][128];
    __shared__ float Bs[16][136];

    int tid = threadIdx.x;
    int bm = blockIdx.y * 128;
    int bn = blockIdx.x * 128;
    int tx = tid & 15;
    int ty = tid >> 4;

    float acc[8][8];
    #pragma unroll
    for (int i = 0; i < 8; i++)
        #pragma unroll
        for (int j = 0; j < 8; j++) acc[i][j] = 0.0f;

    const float* Ab = A + (size_t)bm * K;
    const float* Bb = B + (size_t)bn * K;

    for (int k0 = 0; k0 < K; k0 += 16) {
        #pragma unroll
        for (int i = 0; i < 2; i++) {
            int q   = tid + i * 256;
            int row = q >> 2;
            int c4  = q & 3;
            float4 a = *(const float4*)(Ab + (size_t)row * K + k0 + c4 * 4);
            As[c4*4+0][row] = a.x; As[c4*4+1][row] = a.y;
            As[c4*4+2][row] = a.z; As[c4*4+3][row] = a.w;
            float4 b = *(const float4*)(Bb + (size_t)row * K + k0 + c4 * 4);
            Bs[c4*4+0][row] = b.x; Bs[c4*4+1][row] = b.y;
            Bs[c4*4+2][row] = b.z; Bs[c4*4+3][row] = b.w;
        }
        __syncthreads();
        #pragma unroll
        for (int k = 0; k < 16; k++) {
            float4 a0 = *(const float4*)&As[k][ty*8];
            float4 a1 = *(const float4*)&As[k][ty*8+4];
            float4 b0 = *(const float4*)&Bs[k][tx*8];
            float4 b1 = *(const float4*)&Bs[k][tx*8+4];
            float av[8] = {a0.x,a0.y,a0.z,a0.w,a1.x,a1.y,a1.z,a1.w};
            float bv[8] = {b0.x,b0.y,b0.z,b0.w,b1.x,b1.y,b1.z,b1.w};
            #pragma unroll
            for (int i = 0; i < 8; i++)
                #pragma unroll
                for (int j = 0; j < 8; j++)
                    acc[i][j] = fmaf(av[i], bv[j], acc[i][j]);
        }
        __syncthreads();
    }

    float bb[8];
    #pragma unroll
    for (int j = 0; j < 8; j++) bb[j] = bias[bn + tx*8 + j];
    #pragma unroll
    for (int i = 0; i < 8; i++) {
        size_t row = (size_t)(bm + ty*8 + i);
        float4 o0 = make_float4(acc[i][0]+bb[0], acc[i][1]+bb[1], acc[i][2]+bb[2], acc[i][3]+bb[3]);
        float4 o1 = make_float4(acc[i][4]+bb[4], acc[i][5]+bb[5], acc[i][6]+bb[6], acc[i][7]+bb[7]);
        *(float4*)(C + row * N + bn + tx*8    ) = o0;
        *(float4*)(C + row * N + bn + tx*8 + 4) = o1;
    }
}

// ---------------- persistent GRU recurrence (per-CTA tag sync) ----------------
// 128 CTAs x 256 threads. CTA b owns units [b*8, b*8+8); warp w owns unit b*8+w.
// W_hh rows in registers. Sync per step:
//   producers: plain-store 8 h floats -> __syncthreads -> tid0 release-stores
//              done[(t+1)&1][b] = t+1   (release-through-barrier, cumulative)
//   consumers: threads 0..127 acquire-poll ONE slot each until == t, then
//              __syncthreads, then one coalesced 4KB load of h.
// Single hop, no atomics, no membar, ~64KB/round chip-wide poll traffic.
__global__ void __launch_bounds__(256, 1) gru_scan(const float* __restrict__ Whh,
                                                   const float* __restrict__ bhh,
                                                   const float* __restrict__ gi,
                                                   float* __restrict__ ys,
                                                   float* __restrict__ hfin,
                                                   float* __restrict__ hfin2,
                                                   int T)
{
    int tid  = threadIdx.x;
    int w    = tid >> 5;
    int lane = tid & 31;
    int b    = blockIdx.x;
    int unit = b * 8 + w;

    const float4* Wr = (const float4*)(Whh + (size_t)unit            * HDIM);
    const float4* Wz = (const float4*)(Whh + (size_t)(HDIM   + unit) * HDIM);
    const float4* Wn = (const float4*)(Whh + (size_t)(2*HDIM + unit) * HDIM);
    float4 wr[8], wz[8], wn[8];
    #pragma unroll
    for (int c = 0; c < 8; c++) {
        wr[c] = Wr[c*32 + lane];
        wz[c] = Wz[c*32 + lane];
        wn[c] = Wn[c*32 + lane];
    }
    float br  = bhh[unit];
    float bz  = bhh[HDIM   + unit];
    float bn_ = bhh[2*HDIM + unit];

    __shared__ __align__(16) float h_s[HDIM];
    __shared__ float gi_s[24];
    float h_last = 0.0f;

    for (int t = 0; t < T; t++) {
        // prefetch this step's input-projection values
        if (tid < 24)
            gi_s[tid] = gi[(size_t)t * G3 + (size_t)(tid >> 3) * HDIM + b*8 + (tid & 7)];

        // wait for all 128 producer CTAs of the previous step
        if (tid < NCTA) {
            const unsigned* slot = &g_done[t & 1][tid];
            while (ldacq_u32(slot) != (unsigned)t) { }
        }
        __syncthreads();

        // one coalesced 4KB load of h -> smem
        float4 hv = ((const float4*)g_hv[t & 1])[tid];
        *(float4*)&h_s[tid * 4] = hv;
        __syncthreads();

        float ar = 0.f, az = 0.f, an = 0.f;
        #pragma unroll
        for (int c = 0; c < 8; c++) {
            float4 h4 = *(const float4*)&h_s[c*128 + lane*4];
            ar = fmaf(wr[c].x,h4.x, fmaf(wr[c].y,h4.y, fmaf(wr[c].z,h4.z, fmaf(wr[c].w,h4.w, ar))));
            az = fmaf(wz[c].x,h4.x, fmaf(wz[c].y,h4.y, fmaf(wz[c].z,h4.z, fmaf(wz[c].w,h4.w, az))));
            an = fmaf(wn[c].x,h4.x, fmaf(wn[c].y,h4.y, fmaf(wn[c].z,h4.z, fmaf(wn[c].w,h4.w, an))));
        }
        #pragma unroll
        for (int o = 16; o; o >>= 1) {
            ar += __shfl_xor_sync(0xffffffffu, ar, o);
            az += __shfl_xor_sync(0xffffffffu, az, o);
            an += __shfl_xor_sync(0xffffffffu, an, o);
        }
        if (lane == 0) {
            float xr = gi_s[w], xz = gi_s[8 + w], xn = gi_s[16 + w];
            float r = fsig(xr + ar + br);
            float z = fsig(xz + az + bz);
            float n = tanhf(xn + r * (an + bn_));
            float hp = h_s[unit];
            float hnw = (1.0f - z) * n + z * hp;
            g_hv[(t + 1) & 1][unit] = hnw;      // plain store
            if (ys) ys[(size_t)t * HDIM + unit] = hnw;
            h_last = hnw;
        }
        __syncthreads();                         // all 8 h stores issued
        if (tid == 0)
            strel_u32(&g_done[(t + 1) & 1][b], (unsigned)(t + 1));
    }

    if (lane == 0) {
        hfin[unit] = h_last;
        if (hfin2) hfin2[unit] = h_last;
    }
}

// reset state: h_0 = 0 in both buffers, tags = 0 (tag 0 == "h_0 ready")
__global__ void zero_state_kernel()
{
    g_hv[0][threadIdx.x] = 0.0f;
    g_hv[1][threadIdx.x] = 0.0f;
    if (threadIdx.x < NCTA) {
        g_done[0][threadIdx.x] = 0u;
        g_done[1][threadIdx.x] = 0u;
    }
}

// ---------------- launch -----------------------------------------------------
extern "C" void kernel_launch(void* const* d_in, const int* in_sizes, int n_in,
                              void* d_out, int out_size)
{
    const int*   idx  = (const int*)  d_in[0];
    const float* E    = (const float*)d_in[1];
    const float* Wih0 = (const float*)d_in[2];
    const float* Whh0 = (const float*)d_in[3];
    const float* bih0 = (const float*)d_in[4];
    const float* bhh0 = (const float*)d_in[5];
    const float* Wih1 = (const float*)d_in[6];
    const float* Whh1 = (const float*)d_in[7];
    const float* bih1 = (const float*)d_in[8];
    const float* bhh1 = (const float*)d_in[9];
    float* out = (float*)d_out;

    float *emb, *gi, *ysv;
    cudaGetSymbolAddress((void**)&emb, g_emb);
    cudaGetSymbolAddress((void**)&gi,  g_gi);
    cudaGetSymbolAddress((void**)&ysv, g_ys);

    // 1) embedding + max-norm
    embed_kernel<<<L_SEQ, 128>>>(idx, E, emb);

    // 2) layer-0 input projection: gi = emb @ Wih0^T + bih0
    gemm_tn<<<dim3(G3/128, L_SEQ/128), 256>>>(emb, Wih0, bih0, gi, L_SEQ, G3, EDIM);

    // 3) layer-0 recurrence -> ys1, h1 (h1 -> out[1024:2048])
    zero_state_kernel<<<1, 1024>>>();
    gru_scan<<<NCTA, 256>>>(Whh0, bhh0, gi, ysv, out + HDIM, nullptr, L_SEQ);

    // 4) layer-1 input projection: gi = ys1 @ Wih1^T + bih1
    gemm_tn<<<dim3(G3/128, L_SEQ/128), 256>>>(ysv, Wih1, bih1, gi, L_SEQ, G3, HDIM);

    // 5) layer-1 recurrence -> h2 (h2 -> out[2048:3072] and ys2[-1] -> out[0:1024])
    zero_state_kernel<<<1, 1024>>>();
    gru_scan<<<NCTA, 256>>>(Whh1, bhh1, gi, nullptr, out + 2*HDIM, out, L_SEQ);
}

// round 4
// speedup vs baseline: 2.7173x; 2.7173x over previous
#include <cuda_runtime.h>
#include <math.h>

#define L_SEQ 4096
#define EDIM  512
#define HDIM  1024
#define G3    3072   // 3*HDIM
#define NCTA  128

// ---------------- scratch (static device globals; no allocation) -------------
__device__ float g_emb[(size_t)L_SEQ * EDIM];          // 8 MB
__device__ float g_gi [(size_t)L_SEQ * G3];            // 50 MB (reused per layer)
__device__ float g_ys [(size_t)L_SEQ * HDIM];          // 16 MB (layer-0 outputs)
__device__ float g_hv[2][HDIM];                        // double-buffered hidden state
__device__ unsigned g_ctr;                             // monotonic step counter

// ---------------- memory-model helpers ---------------------------------------
__device__ __forceinline__ unsigned ldacq_u32(const unsigned* p)
{
    unsigned v;
    asm volatile("ld.acquire.gpu.global.b32 %0, [%1];" : "=r"(v) : "l"(p) : "memory");
    return v;
}
__device__ __forceinline__ void red_release_add(unsigned* p, unsigned v)
{
    asm volatile("red.release.gpu.global.add.u32 [%0], %1;" :: "l"(p), "r"(v) : "memory");
}
__device__ __forceinline__ float4 ldacq_v4(const float* p)
{
    float4 v;
    asm volatile("ld.acquire.gpu.global.v4.f32 {%0,%1,%2,%3}, [%4];"
                 : "=f"(v.x), "=f"(v.y), "=f"(v.z), "=f"(v.w) : "l"(p) : "memory");
    return v;
}

__device__ __forceinline__ float fsig(float x)
{
    return 1.0f / (1.0f + __expf(-x));
}

// ---------------- embedding + max-norm --------------------------------------
__global__ void embed_kernel(const int* __restrict__ idx,
                             const float* __restrict__ E,
                             float* __restrict__ emb)
{
    int t = blockIdx.x;
    int id = idx[t];
    const float4* row = (const float4*)(E + (size_t)id * EDIM);
    float4 v = row[threadIdx.x];
    float ss = v.x*v.x + v.y*v.y + v.z*v.z + v.w*v.w;
    #pragma unroll
    for (int o = 16; o; o >>= 1) ss += __shfl_xor_sync(0xffffffffu, ss, o);
    __shared__ float red[4];
    int w = threadIdx.x >> 5;
    if ((threadIdx.x & 31) == 0) red[w] = ss;
    __syncthreads();
    float tot = red[0] + red[1] + red[2] + red[3];
    float scale = fminf(1.0f, 1.0f / fmaxf(sqrtf(tot), 1e-7f));
    v.x *= scale; v.y *= scale; v.z *= scale; v.w *= scale;
    ((float4*)(emb + (size_t)t * EDIM))[threadIdx.x] = v;
}

// ---------------- fp32 GEMM: C[M,N] = A[M,K] @ B[N,K]^T + bias[N] -----------
__global__ void __launch_bounds__(256) gemm_tn(const float* __restrict__ A,
                                               const float* __restrict__ B,
                                               const float* __restrict__ bias,
                                               float* __restrict__ C,
                                               int M, int N, int K)
{
    __shared__ float As[16][128];
    __shared__ float Bs[16][136];

    int tid = threadIdx.x;
    int bm = blockIdx.y * 128;
    int bn = blockIdx.x * 128;
    int tx = tid & 15;
    int ty = tid >> 4;

    float acc[8][8];
    #pragma unroll
    for (int i = 0; i < 8; i++)
        #pragma unroll
        for (int j = 0; j < 8; j++) acc[i][j] = 0.0f;

    const float* Ab = A + (size_t)bm * K;
    const float* Bb = B + (size_t)bn * K;

    for (int k0 = 0; k0 < K; k0 += 16) {
        #pragma unroll
        for (int i = 0; i < 2; i++) {
            int q   = tid + i * 256;
            int row = q >> 2;
            int c4  = q & 3;
            float4 a = *(const float4*)(Ab + (size_t)row * K + k0 + c4 * 4);
            As[c4*4+0][row] = a.x; As[c4*4+1][row] = a.y;
            As[c4*4+2][row] = a.z; As[c4*4+3][row] = a.w;
            float4 b = *(const float4*)(Bb + (size_t)row * K + k0 + c4 * 4);
            Bs[c4*4+0][row] = b.x; Bs[c4*4+1][row] = b.y;
            Bs[c4*4+2][row] = b.z; Bs[c4*4+3][row] = b.w;
        }
        __syncthreads();
        #pragma unroll
        for (int k = 0; k < 16; k++) {
            float4 a0 = *(const float4*)&As[k][ty*8];
            float4 a1 = *(const float4*)&As[k][ty*8+4];
            float4 b0 = *(const float4*)&Bs[k][tx*8];
            float4 b1 = *(const float4*)&Bs[k][tx*8+4];
            float av[8] = {a0.x,a0.y,a0.z,a0.w,a1.x,a1.y,a1.z,a1.w};
            float bv[8] = {b0.x,b0.y,b0.z,b0.w,b1.x,b1.y,b1.z,b1.w};
            #pragma unroll
            for (int i = 0; i < 8; i++)
                #pragma unroll
                for (int j = 0; j < 8; j++)
                    acc[i][j] = fmaf(av[i], bv[j], acc[i][j]);
        }
        __syncthreads();
    }

    float bb[8];
    #pragma unroll
    for (int j = 0; j < 8; j++) bb[j] = bias[bn + tx*8 + j];
    #pragma unroll
    for (int i = 0; i < 8; i++) {
        size_t row = (size_t)(bm + ty*8 + i);
        float4 o0 = make_float4(acc[i][0]+bb[0], acc[i][1]+bb[1], acc[i][2]+bb[2], acc[i][3]+bb[3]);
        float4 o1 = make_float4(acc[i][4]+bb[4], acc[i][5]+bb[5], acc[i][6]+bb[6], acc[i][7]+bb[7]);
        *(float4*)(C + row * N + bn + tx*8    ) = o0;
        *(float4*)(C + row * N + bn + tx*8 + 4) = o1;
    }
}

// ---------------- persistent GRU recurrence (REDG counter barrier) ------------
// 128 CTAs x 256 threads. CTA b owns units [b*8, b*8+8); warp w owns unit b*8+w.
// W_hh rows in registers. Per-step sync:
//   end of step: __syncthreads; tid0: red.release.gpu.add(ctr, 1)   [no return]
//   top of step t: tid0 acquire-polls ctr >= 128*t; __syncthreads.
// One hot line, read-broadcast polls, ~110cyc aggregate arrival, no membar.
// Buffer safety: ctr>=128*t  =>  every CTA finished step t-1  =>  every CTA
// already consumed buffer (t-1)&1, so writes to buffer (t+1)&1 (same parity)
// cannot race step-(t-1) readers.
__global__ void __launch_bounds__(256, 1) gru_scan(const float* __restrict__ Whh,
                                                   const float* __restrict__ bhh,
                                                   const float* __restrict__ gi,
                                                   float* __restrict__ ys,
                                                   float* __restrict__ hfin,
                                                   float* __restrict__ hfin2,
                                                   int T)
{
    int tid  = threadIdx.x;
    int w    = tid >> 5;
    int lane = tid & 31;
    int b    = blockIdx.x;
    int unit = b * 8 + w;

    const float4* Wr = (const float4*)(Whh + (size_t)unit            * HDIM);
    const float4* Wz = (const float4*)(Whh + (size_t)(HDIM   + unit) * HDIM);
    const float4* Wn = (const float4*)(Whh + (size_t)(2*HDIM + unit) * HDIM);
    float4 wr[8], wz[8], wn[8];
    #pragma unroll
    for (int c = 0; c < 8; c++) {
        wr[c] = Wr[c*32 + lane];
        wz[c] = Wz[c*32 + lane];
        wn[c] = Wn[c*32 + lane];
    }
    float br  = bhh[unit];
    float bz  = bhh[HDIM   + unit];
    float bn_ = bhh[2*HDIM + unit];

    __shared__ __align__(16) float h_s[HDIM];
    __shared__ float gi_s[24];
    float h_last = 0.0f;

    for (int t = 0; t < T; t++) {
        // prefetch this step's input-projection values (overlaps the poll)
        if (tid < 24)
            gi_s[tid] = gi[(size_t)t * G3 + (size_t)(tid >> 3) * HDIM + b*8 + (tid & 7)];

        // wait: all CTAs completed step t-1
        if (tid == 0) {
            unsigned target = (unsigned)t * NCTA;
            while ((int)(ldacq_u32(&g_ctr) - target) < 0) { }
        }
        __syncthreads();

        // one 128-bit strong load of h -> smem
        float4 hv = ldacq_v4(&g_hv[t & 1][tid * 4]);
        *(float4*)&h_s[tid * 4] = hv;
        __syncthreads();

        float ar = 0.f, az = 0.f, an = 0.f;
        #pragma unroll
        for (int c = 0; c < 8; c++) {
            float4 h4 = *(const float4*)&h_s[c*128 + lane*4];
            ar = fmaf(wr[c].x,h4.x, fmaf(wr[c].y,h4.y, fmaf(wr[c].z,h4.z, fmaf(wr[c].w,h4.w, ar))));
            az = fmaf(wz[c].x,h4.x, fmaf(wz[c].y,h4.y, fmaf(wz[c].z,h4.z, fmaf(wz[c].w,h4.w, az))));
            an = fmaf(wn[c].x,h4.x, fmaf(wn[c].y,h4.y, fmaf(wn[c].z,h4.z, fmaf(wn[c].w,h4.w, an))));
        }
        #pragma unroll
        for (int o = 16; o; o >>= 1) {
            ar += __shfl_xor_sync(0xffffffffu, ar, o);
            az += __shfl_xor_sync(0xffffffffu, az, o);
            an += __shfl_xor_sync(0xffffffffu, an, o);
        }
        if (lane == 0) {
            float xr = gi_s[w], xz = gi_s[8 + w], xn = gi_s[16 + w];
            float r = fsig(xr + ar + br);
            float z = fsig(xz + az + bz);
            float n = tanhf(xn + r * (an + bn_));
            float hp = h_s[unit];
            float hnw = (1.0f - z) * n + z * hp;
            g_hv[(t + 1) & 1][unit] = hnw;      // plain store; ordered by bar+red.release
            if (ys) ys[(size_t)t * HDIM + unit] = hnw;
            h_last = hnw;
        }
        __syncthreads();                         // all 8 unit stores before arrive
        if (tid == 0)
            red_release_add(&g_ctr, 1u);
    }

    if (lane == 0) {
        hfin[unit] = h_last;
        if (hfin2) hfin2[unit] = h_last;
    }
}

// reset: h_0 = 0 in both buffers, counter = 0
__global__ void zero_state_kernel()
{
    g_hv[0][threadIdx.x] = 0.0f;
    g_hv[1][threadIdx.x] = 0.0f;
    if (threadIdx.x == 0) g_ctr = 0u;
}

// ---------------- launch -----------------------------------------------------
extern "C" void kernel_launch(void* const* d_in, const int* in_sizes, int n_in,
                              void* d_out, int out_size)
{
    const int*   idx  = (const int*)  d_in[0];
    const float* E    = (const float*)d_in[1];
    const float* Wih0 = (const float*)d_in[2];
    const float* Whh0 = (const float*)d_in[3];
    const float* bih0 = (const float*)d_in[4];
    const float* bhh0 = (const float*)d_in[5];
    const float* Wih1 = (const float*)d_in[6];
    const float* Whh1 = (const float*)d_in[7];
    const float* bih1 = (const float*)d_in[8];
    const float* bhh1 = (const float*)d_in[9];
    float* out = (float*)d_out;

    float *emb, *gi, *ysv;
    cudaGetSymbolAddress((void**)&emb, g_emb);
    cudaGetSymbolAddress((void**)&gi,  g_gi);
    cudaGetSymbolAddress((void**)&ysv, g_ys);

    // 1) embedding + max-norm
    embed_kernel<<<L_SEQ, 128>>>(idx, E, emb);

    // 2) layer-0 input projection: gi = emb @ Wih0^T + bih0
    gemm_tn<<<dim3(G3/128, L_SEQ/128), 256>>>(emb, Wih0, bih0, gi, L_SEQ, G3, EDIM);

    // 3) layer-0 recurrence -> ys1, h1 (h1 -> out[1024:2048])
    zero_state_kernel<<<1, 1024>>>();
    gru_scan<<<NCTA, 256>>>(Whh0, bhh0, gi, ysv, out + HDIM, nullptr, L_SEQ);

    // 4) layer-1 input projection: gi = ys1 @ Wih1^T + bih1
    gemm_tn<<<dim3(G3/128, L_SEQ/128), 256>>>(ysv, Wih1, bih1, gi, L_SEQ, G3, HDIM);

    // 5) layer-1 recurrence -> h2 (h2 -> out[2048:3072] and ys2[-1] -> out[0:1024])
    zero_state_kernel<<<1, 1024>>>();
    gru_scan<<<NCTA, 256>>>(Whh1, bhh1, gi, nullptr, out + 2*HDIM, out, L_SEQ);
}

// round 5
// speedup vs baseline: 2.8683x; 1.0556x over previous
#include <cuda_runtime.h>
#include <math.h>

#define L_SEQ 4096
#define EDIM  512
#define HDIM  1024
#define G3    3072   // 3*HDIM
#define NCTA  128

// ---------------- scratch (static device globals; no allocation) -------------
__device__ float g_emb[(size_t)L_SEQ * EDIM];          // 8 MB
__device__ float g_gi [(size_t)L_SEQ * G3];            // 50 MB (reused per layer)
__device__ float g_ys [(size_t)L_SEQ * HDIM];          // 16 MB (layer-0 outputs)
__device__ float g_hv[2][HDIM];                        // double-buffered hidden state
__device__ unsigned g_ctr;                             // monotonic step counter

// ---------------- memory-model helpers ---------------------------------------
__device__ __forceinline__ unsigned ldacq_u32(const unsigned* p)
{
    unsigned v;
    asm volatile("ld.acquire.gpu.global.b32 %0, [%1];" : "=r"(v) : "l"(p) : "memory");
    return v;
}
__device__ __forceinline__ void red_release_add(unsigned* p, unsigned v)
{
    asm volatile("red.release.gpu.global.add.u32 [%0], %1;" :: "l"(p), "r"(v) : "memory");
}
__device__ __forceinline__ float4 ldacq_v4(const float* p)
{
    float4 v;
    asm volatile("ld.acquire.gpu.global.v4.f32 {%0,%1,%2,%3}, [%4];"
                 : "=f"(v.x), "=f"(v.y), "=f"(v.z), "=f"(v.w) : "l"(p) : "memory");
    return v;
}

// ---------------- packed f32x2 helpers (sm_103a; ptxas never emits these) -----
__device__ __forceinline__ unsigned long long pack2(float x, float y)
{
    unsigned long long r;
    asm("mov.b64 %0, {%1, %2};" : "=l"(r) : "f"(x), "f"(y));
    return r;
}
__device__ __forceinline__ unsigned long long fma2(unsigned long long a,
                                                   unsigned long long b,
                                                   unsigned long long c)
{
    unsigned long long d;
    asm("fma.rn.f32x2 %0, %1, %2, %3;" : "=l"(d) : "l"(a), "l"(b), "l"(c));
    return d;
}
__device__ __forceinline__ float2 unpack2(unsigned long long v)
{
    float2 f;
    asm("mov.b64 {%0, %1}, %2;" : "=f"(f.x), "=f"(f.y) : "l"(v));
    return f;
}

// fast saturation-safe activations (budget: rel_err < 1e-3; these are ~1e-6)
__device__ __forceinline__ float fsig(float x)
{
    return __fdividef(1.0f, 1.0f + __expf(-x));   // x->+inf: 1; x->-inf: 0
}
__device__ __forceinline__ float ftanh(float x)
{
    // tanh = 1 - 2/(1+e^{2x});  e^{2x}->inf => 1;  e^{2x}->0 => -1
    return 1.0f - __fdividef(2.0f, 1.0f + __expf(2.0f * x));
}

// ---------------- embedding + max-norm --------------------------------------
__global__ void embed_kernel(const int* __restrict__ idx,
                             const float* __restrict__ E,
                             float* __restrict__ emb)
{
    int t = blockIdx.x;
    int id = idx[t];
    const float4* row = (const float4*)(E + (size_t)id * EDIM);
    float4 v = row[threadIdx.x];
    float ss = v.x*v.x + v.y*v.y + v.z*v.z + v.w*v.w;
    #pragma unroll
    for (int o = 16; o; o >>= 1) ss += __shfl_xor_sync(0xffffffffu, ss, o);
    __shared__ float red[4];
    int w = threadIdx.x >> 5;
    if ((threadIdx.x & 31) == 0) red[w] = ss;
    __syncthreads();
    float tot = red[0] + red[1] + red[2] + red[3];
    float scale = fminf(1.0f, 1.0f / fmaxf(sqrtf(tot), 1e-7f));
    v.x *= scale; v.y *= scale; v.z *= scale; v.w *= scale;
    ((float4*)(emb + (size_t)t * EDIM))[threadIdx.x] = v;
}

// ---------------- fp32 GEMM (f32x2 inner): C = A @ B^T + bias ----------------
__global__ void __launch_bounds__(256) gemm_tn(const float* __restrict__ A,
                                               const float* __restrict__ B,
                                               const float* __restrict__ bias,
                                               float* __restrict__ C,
                                               int M, int N, int K)
{
    __shared__ float As[16][128];
    __shared__ float Bs[16][136];

    int tid = threadIdx.x;
    int bm = blockIdx.y * 128;
    int bn = blockIdx.x * 128;
    int tx = tid & 15;
    int ty = tid >> 4;

    unsigned long long acc2[8][4];
    #pragma unroll
    for (int i = 0; i < 8; i++)
        #pragma unroll
        for (int j = 0; j < 4; j++) acc2[i][j] = 0ull;

    const float* Ab = A + (size_t)bm * K;
    const float* Bb = B + (size_t)bn * K;

    for (int k0 = 0; k0 < K; k0 += 16) {
        #pragma unroll
        for (int i = 0; i < 2; i++) {
            int q   = tid + i * 256;
            int row = q >> 2;
            int c4  = q & 3;
            float4 a = *(const float4*)(Ab + (size_t)row * K + k0 + c4 * 4);
            As[c4*4+0][row] = a.x; As[c4*4+1][row] = a.y;
            As[c4*4+2][row] = a.z; As[c4*4+3][row] = a.w;
            float4 b = *(const float4*)(Bb + (size_t)row * K + k0 + c4 * 4);
            Bs[c4*4+0][row] = b.x; Bs[c4*4+1][row] = b.y;
            Bs[c4*4+2][row] = b.z; Bs[c4*4+3][row] = b.w;
        }
        __syncthreads();
        #pragma unroll
        for (int k = 0; k < 16; k++) {
            float4 a0 = *(const float4*)&As[k][ty*8];
            float4 a1 = *(const float4*)&As[k][ty*8+4];
            float4 b0 = *(const float4*)&Bs[k][tx*8];
            float4 b1 = *(const float4*)&Bs[k][tx*8+4];
            float av[8] = {a0.x,a0.y,a0.z,a0.w,a1.x,a1.y,a1.z,a1.w};
            unsigned long long bp[4] = { pack2(b0.x,b0.y), pack2(b0.z,b0.w),
                                         pack2(b1.x,b1.y), pack2(b1.z,b1.w) };
            #pragma unroll
            for (int i = 0; i < 8; i++) {
                unsigned long long ad = pack2(av[i], av[i]);
                #pragma unroll
                for (int j = 0; j < 4; j++)
                    acc2[i][j] = fma2(ad, bp[j], acc2[i][j]);
            }
        }
        __syncthreads();
    }

    float bb[8];
    #pragma unroll
    for (int j = 0; j < 8; j++) bb[j] = bias[bn + tx*8 + j];
    #pragma unroll
    for (int i = 0; i < 8; i++) {
        size_t row = (size_t)(bm + ty*8 + i);
        float2 c0 = unpack2(acc2[i][0]);
        float2 c1 = unpack2(acc2[i][1]);
        float2 c2 = unpack2(acc2[i][2]);
        float2 c3 = unpack2(acc2[i][3]);
        float4 o0 = make_float4(c0.x+bb[0], c0.y+bb[1], c1.x+bb[2], c1.y+bb[3]);
        float4 o1 = make_float4(c2.x+bb[4], c2.y+bb[5], c3.x+bb[6], c3.y+bb[7]);
        *(float4*)(C + row * N + bn + tx*8    ) = o0;
        *(float4*)(C + row * N + bn + tx*8 + 4) = o1;
    }
}

// ---------------- persistent GRU recurrence (REDG barrier + f32x2 math) -------
// 128 CTAs x 256 threads. CTA b owns units [b*8, b*8+8); warp w owns unit b*8+w.
// W_hh rows live in registers as packed f32x2 pairs (48 FFMA2/step vs 96 FFMA).
__global__ void __launch_bounds__(256, 1) gru_scan(const float* __restrict__ Whh,
                                                   const float* __restrict__ bhh,
                                                   const float* __restrict__ gi,
                                                   float* __restrict__ ys,
                                                   float* __restrict__ hfin,
                                                   float* __restrict__ hfin2,
                                                   int T)
{
    int tid  = threadIdx.x;
    int w    = tid >> 5;
    int lane = tid & 31;
    int b    = blockIdx.x;
    int unit = b * 8 + w;

    // weights as packed pairs: lane covers h elements [c*128+lane*4, +4)
    const ulonglong2* Wr = (const ulonglong2*)(Whh + (size_t)unit            * HDIM);
    const ulonglong2* Wz = (const ulonglong2*)(Whh + (size_t)(HDIM   + unit) * HDIM);
    const ulonglong2* Wn = (const ulonglong2*)(Whh + (size_t)(2*HDIM + unit) * HDIM);
    ulonglong2 wr2[8], wz2[8], wn2[8];
    #pragma unroll
    for (int c = 0; c < 8; c++) {
        wr2[c] = Wr[c*32 + lane];
        wz2[c] = Wz[c*32 + lane];
        wn2[c] = Wn[c*32 + lane];
    }
    float br  = bhh[unit];
    float bz  = bhh[HDIM   + unit];
    float bn_ = bhh[2*HDIM + unit];

    __shared__ __align__(16) float h_s[HDIM];
    __shared__ float gi_s[24];
    float h_last = 0.0f;

    for (int t = 0; t < T; t++) {
        // prefetch this step's input-projection values (overlaps the poll)
        if (tid < 24)
            gi_s[tid] = gi[(size_t)t * G3 + (size_t)(tid >> 3) * HDIM + b*8 + (tid & 7)];

        // wait: all CTAs completed step t-1 (single hot line, read-broadcast)
        if (tid == 0) {
            unsigned target = (unsigned)t * NCTA;
            while ((int)(ldacq_u32(&g_ctr) - target) < 0) { }
        }
        __syncthreads();

        // one 128-bit strong load of h -> smem
        float4 hv = ldacq_v4(&g_hv[t & 1][tid * 4]);
        *(float4*)&h_s[tid * 4] = hv;
        __syncthreads();

        unsigned long long ar2 = 0ull, az2 = 0ull, an2 = 0ull;
        #pragma unroll
        for (int c = 0; c < 8; c++) {
            ulonglong2 h2 = *(const ulonglong2*)&h_s[c*128 + lane*4];
            ar2 = fma2(wr2[c].x, h2.x, ar2);
            az2 = fma2(wz2[c].x, h2.x, az2);
            an2 = fma2(wn2[c].x, h2.x, an2);
            ar2 = fma2(wr2[c].y, h2.y, ar2);
            az2 = fma2(wz2[c].y, h2.y, az2);
            an2 = fma2(wn2[c].y, h2.y, an2);
        }
        float2 fr = unpack2(ar2);
        float2 fz = unpack2(az2);
        float2 fn = unpack2(an2);
        float ar = fr.x + fr.y;
        float az = fz.x + fz.y;
        float an = fn.x + fn.y;
        #pragma unroll
        for (int o = 16; o; o >>= 1) {
            ar += __shfl_xor_sync(0xffffffffu, ar, o);
            az += __shfl_xor_sync(0xffffffffu, az, o);
            an += __shfl_xor_sync(0xffffffffu, an, o);
        }

        // all lanes compute the gate chain (no serial lane-0 MUFU path)
        float xr = gi_s[w], xz = gi_s[8 + w], xn = gi_s[16 + w];
        float r = fsig(xr + ar + br);
        float z = fsig(xz + az + bz);
        float n = ftanh(xn + r * (an + bn_));
        float hp = h_s[unit];
        float hnw = (1.0f - z) * n + z * hp;
        if (lane == 0) {
            g_hv[(t + 1) & 1][unit] = hnw;      // plain store; ordered by bar+red.release
            if (ys) ys[(size_t)t * HDIM + unit] = hnw;
            h_last = hnw;
        }
        __syncthreads();                         // all 8 unit stores before arrive
        if (tid == 0)
            red_release_add(&g_ctr, 1u);
    }

    if (lane == 0) {
        hfin[unit] = h_last;
        if (hfin2) hfin2[unit] = h_last;
    }
}

// reset: h_0 = 0 in both buffers, counter = 0
__global__ void zero_state_kernel()
{
    g_hv[0][threadIdx.x] = 0.0f;
    g_hv[1][threadIdx.x] = 0.0f;
    if (threadIdx.x == 0) g_ctr = 0u;
}

// ---------------- launch -----------------------------------------------------
extern "C" void kernel_launch(void* const* d_in, const int* in_sizes, int n_in,
                              void* d_out, int out_size)
{
    const int*   idx  = (const int*)  d_in[0];
    const float* E    = (const float*)d_in[1];
    const float* Wih0 = (const float*)d_in[2];
    const float* Whh0 = (const float*)d_in[3];
    const float* bih0 = (const float*)d_in[4];
    const float* bhh0 = (const float*)d_in[5];
    const float* Wih1 = (const float*)d_in[6];
    const float* Whh1 = (const float*)d_in[7];
    const float* bih1 = (const float*)d_in[8];
    const float* bhh1 = (const float*)d_in[9];
    float* out = (float*)d_out;

    float *emb, *gi, *ysv;
    cudaGetSymbolAddress((void**)&emb, g_emb);
    cudaGetSymbolAddress((void**)&gi,  g_gi);
    cudaGetSymbolAddress((void**)&ysv, g_ys);

    // 1) embedding + max-norm
    embed_kernel<<<L_SEQ, 128>>>(idx, E, emb);

    // 2) layer-0 input projection: gi = emb @ Wih0^T + bih0
    gemm_tn<<<dim3(G3/128, L_SEQ/128), 256>>>(emb, Wih0, bih0, gi, L_SEQ, G3, EDIM);

    // 3) layer-0 recurrence -> ys1, h1 (h1 -> out[1024:2048])
    zero_state_kernel<<<1, 1024>>>();
    gru_scan<<<NCTA, 256>>>(Whh0, bhh0, gi, ysv, out + HDIM, nullptr, L_SEQ);

    // 4) layer-1 input projection: gi = ys1 @ Wih1^T + bih1
    gemm_tn<<<dim3(G3/128, L_SEQ/128), 256>>>(ysv, Wih1, bih1, gi, L_SEQ, G3, HDIM);

    // 5) layer-1 recurrence -> h2 (h2 -> out[2048:3072] and ys2[-1] -> out[0:1024])
    zero_state_kernel<<<1, 1024>>>();
    gru_scan<<<NCTA, 256>>>(Whh1, bhh1, gi, nullptr, out + 2*HDIM, out, L_SEQ);
}